// round 2
// baseline (speedup 1.0000x reference)
#include <cuda_runtime.h>
#include <math.h>

#define BATCH 8
#define CIN   512
#define HW    1024
#define DQKV  768
#define DVDIM 256
#define COUT  512

// Scratch (static device globals: allocation-free rule)
__device__ float g_qkv[(size_t)BATCH * DQKV * HW];   // 24 MB: [b][o][s], Q rows pre-scaled
__device__ float g_attn[(size_t)BATCH * DVDIM * HW]; // 8 MB:  [b][c][s] (reference-reshape layout)

// ---------------------------------------------------------------------------
// Generic batched GEMM: C[b][o][s] = sum_c W[o][c] * X[b][c][s] + bias[o]
// rows o < scale_limit additionally multiplied by `scale` (for Q pre-scaling).
// 128x128 tile, 256 threads, 8x8 per thread, BK=16.
// ---------------------------------------------------------------------------
template<int K>
__global__ __launch_bounds__(256) void gemm_bias_kernel(
    const float* __restrict__ Wm, const float* __restrict__ X,
    const float* __restrict__ bias, float* __restrict__ C,
    int M, int N, int scale_limit, float scale)
{
    __shared__ float Ws[16][132];
    __shared__ float Xs[16][132];
    const int b  = blockIdx.z;
    const int m0 = blockIdx.y * 128;
    const int n0 = blockIdx.x * 128;
    const float* Xb = X + (size_t)b * K * N;
    float*       Cb = C + (size_t)b * M * N;
    const int tid = threadIdx.x;
    const int tx = tid & 15, ty = tid >> 4;

    float acc[8][8] = {};

    for (int kt = 0; kt < K; kt += 16) {
        // W tile [128 rows][16 c] -> transposed into Ws[c][row]
        {
            const int c4 = (tid & 3) * 4;
            const int r  = tid >> 2;            // 0..63
            #pragma unroll
            for (int rr = 0; rr < 128; rr += 64) {
                float4 v = *(const float4*)&Wm[(size_t)(m0 + r + rr) * K + kt + c4];
                Ws[c4 + 0][r + rr] = v.x;
                Ws[c4 + 1][r + rr] = v.y;
                Ws[c4 + 2][r + rr] = v.z;
                Ws[c4 + 3][r + rr] = v.w;
            }
            const int s4 = (tid & 31) * 4;
            const int cr = tid >> 5;            // 0..7
            #pragma unroll
            for (int cc = 0; cc < 16; cc += 8) {
                float4 v = *(const float4*)&Xb[(size_t)(kt + cr + cc) * N + n0 + s4];
                *(float4*)&Xs[cr + cc][s4] = v;
            }
        }
        __syncthreads();
        #pragma unroll
        for (int kk = 0; kk < 16; kk++) {
            float a[8], bb[8];
            *(float4*)&a[0]  = *(const float4*)&Ws[kk][ty * 8];
            *(float4*)&a[4]  = *(const float4*)&Ws[kk][ty * 8 + 4];
            *(float4*)&bb[0] = *(const float4*)&Xs[kk][tx * 8];
            *(float4*)&bb[4] = *(const float4*)&Xs[kk][tx * 8 + 4];
            #pragma unroll
            for (int i = 0; i < 8; i++)
                #pragma unroll
                for (int j = 0; j < 8; j++)
                    acc[i][j] += a[i] * bb[j];
        }
        __syncthreads();
    }

    #pragma unroll
    for (int i = 0; i < 8; i++) {
        const int row = m0 + ty * 8 + i;
        const float bv = bias[row];
        const float sc = (row < scale_limit) ? scale : 1.0f;
        #pragma unroll
        for (int j = 0; j < 8; j++) {
            Cb[(size_t)row * N + n0 + tx * 8 + j] = (acc[i][j] + bv) * sc;
        }
    }
}

// ---------------------------------------------------------------------------
// Fused attention with head-axis softmax.
// Per CTA: (batch b, 64-query tile). Streams 32-key tiles of K and V.
// softmax over the 8 heads is local per (q,k) -> thread-local (thread owns
// a 2q x 4k patch for ALL 8 heads).
//
// Output written in the REFERENCE's reshape layout:
//   attn_out[b][ h*32 + (q>>5) ][ (q&31)*32 + d ]
// (the reference's reshape of (b,n,q,d) -> (b,NH,32,h,w) scrambles q into the
//  channel axis and d into the spatial axis).
// ---------------------------------------------------------------------------
#define QT   64
#define KTS  32
#define QPAD 260          // row stride for Qs / Vs (floats), 16B-aligned rows
#define KPAD 36           // row stride for Ks (floats)
#define WPAD 33

// smem floats: Qs 64*260 + Ks 256*36 + Vs 32*260 + Wt 8*64*33
#define ATTN_SMEM_FLOATS (64*QPAD + 256*KPAD + 32*QPAD + 8*64*WPAD)

__global__ __launch_bounds__(256) void attn_kernel(float* __restrict__ attn_out)
{
    extern __shared__ float sm[];
    float* Qs = sm;                    // [64][QPAD]  dim-minor
    float* Ks = Qs + 64 * QPAD;        // [256][KPAD] k-minor
    float* Vs = Ks + 256 * KPAD;       // [32][QPAD]  dim-minor
    float* Wt = Vs + 32 * QPAD;        // [8][64][WPAD]

    const int b     = blockIdx.y;
    const int qbase = blockIdx.x * QT;
    const int tid   = threadIdx.x;
    const float* qkv = g_qkv + (size_t)b * DQKV * HW;

    // Load Q tile: Qs[q][dim] = qkv[b][dim][qbase+q]   (dim in [0,256))
    for (int idx = tid; idx < QT * 256; idx += 256) {
        const int dim = idx >> 6;
        const int q   = idx & 63;
        Qs[q * QPAD + dim] = qkv[(size_t)dim * HW + qbase + q];
    }

    const int qg = tid >> 3;     // 0..31 -> 2 q rows each
    const int kg = tid & 7;      // 0..7  -> 4 k cols each (logits phase)
    const int dg = tid & 7;      // 0..7  -> 4 d cols per head (AV phase)
    const int q0 = qg * 2;
    const int k0 = kg * 4;

    float acc[8][2][4] = {};     // [head][qi][dj] persistent output accumulator

    for (int kt = 0; kt < HW; kt += KTS) {
        __syncthreads();   // previous AV done consuming Vs/Wt before reload
        // K tile: Ks[dim][k] ; V tile: Vs[k][dim]
        for (int idx = tid; idx < 256 * KTS; idx += 256) {
            const int dim = idx >> 5;
            const int k   = idx & 31;
            Ks[dim * KPAD + k] = qkv[(size_t)(256 + dim) * HW + kt + k];
        }
        for (int idx = tid; idx < 256 * KTS; idx += 256) {
            const int dim = idx >> 5;
            const int k   = idx & 31;
            Vs[k * QPAD + dim] = qkv[(size_t)(512 + dim) * HW + kt + k];
        }
        __syncthreads();

        // ---- logits: lg[h][qi][kj] = sum_d Q[q0+qi][h*32+d] * K[h*32+d][k0+kj]
        float lg[8][2][4] = {};
        #pragma unroll
        for (int h = 0; h < 8; h++) {
            const float* Kh = &Ks[(h * 32) * KPAD + k0];
            const float* Q0 = &Qs[q0 * QPAD + h * 32];
            const float* Q1 = &Qs[(q0 + 1) * QPAD + h * 32];
            #pragma unroll 8
            for (int d = 0; d < 32; d++) {
                const float4 kv = *(const float4*)&Kh[d * KPAD];
                const float qa = Q0[d];
                const float qb = Q1[d];
                lg[h][0][0] += qa * kv.x; lg[h][0][1] += qa * kv.y;
                lg[h][0][2] += qa * kv.z; lg[h][0][3] += qa * kv.w;
                lg[h][1][0] += qb * kv.x; lg[h][1][1] += qb * kv.y;
                lg[h][1][2] += qb * kv.z; lg[h][1][3] += qb * kv.w;
            }
        }

        // ---- softmax across heads (thread-local), write weights to smem
        #pragma unroll
        for (int qi = 0; qi < 2; qi++) {
            #pragma unroll
            for (int kj = 0; kj < 4; kj++) {
                float m = lg[0][qi][kj];
                #pragma unroll
                for (int h = 1; h < 8; h++) m = fmaxf(m, lg[h][qi][kj]);
                float e[8], s = 0.0f;
                #pragma unroll
                for (int h = 0; h < 8; h++) { e[h] = __expf(lg[h][qi][kj] - m); s += e[h]; }
                const float inv = 1.0f / s;
                #pragma unroll
                for (int h = 0; h < 8; h++)
                    Wt[(h * 64 + q0 + qi) * WPAD + k0 + kj] = e[h] * inv;
            }
        }
        __syncthreads();

        // ---- AV: acc[h][qi][dj] += sum_k Wt[h][q][k] * V[k][h*32+dg*4+dj]
        #pragma unroll
        for (int h = 0; h < 8; h++) {
            const float* Wh0 = &Wt[(h * 64 + q0) * WPAD];
            const float* Wh1 = &Wt[(h * 64 + q0 + 1) * WPAD];
            const float* Vh  = &Vs[h * 32 + dg * 4];
            #pragma unroll 8
            for (int k = 0; k < KTS; k++) {
                const float4 v = *(const float4*)&Vh[k * QPAD];
                const float w0 = Wh0[k];
                const float w1 = Wh1[k];
                acc[h][0][0] += w0 * v.x; acc[h][0][1] += w0 * v.y;
                acc[h][0][2] += w0 * v.z; acc[h][0][3] += w0 * v.w;
                acc[h][1][0] += w1 * v.x; acc[h][1][1] += w1 * v.y;
                acc[h][1][2] += w1 * v.z; acc[h][1][3] += w1 * v.w;
            }
        }
    }

    // Epilogue in the reference's reshape layout:
    //   channel = h*32 + (qq>>5), spatial = (qq&31)*32 + dd
    // dd = dg*4 + j contiguous in j -> float4 store (16B aligned).
    float* ab = attn_out + (size_t)b * DVDIM * HW;
    #pragma unroll
    for (int h = 0; h < 8; h++) {
        #pragma unroll
        for (int qi = 0; qi < 2; qi++) {
            const int qq = qbase + q0 + qi;
            const int ch = h * 32 + (qq >> 5);
            const int sp = (qq & 31) * 32 + dg * 4;
            float4 v;
            v.x = acc[h][qi][0]; v.y = acc[h][qi][1];
            v.z = acc[h][qi][2]; v.w = acc[h][qi][3];
            *(float4*)&ab[(size_t)ch * HW + sp] = v;
        }
    }
}

// ---------------------------------------------------------------------------
extern "C" void kernel_launch(void* const* d_in, const int* in_sizes, int n_in,
                              void* d_out, int out_size)
{
    const float* x      = (const float*)d_in[0];
    const float* w_qkv  = (const float*)d_in[1];
    const float* b_qkv  = (const float*)d_in[2];
    const float* w_attn = (const float*)d_in[3];
    const float* b_attn = (const float*)d_in[4];
    float* out = (float*)d_out;

    float* qkv;  cudaGetSymbolAddress((void**)&qkv,  g_qkv);
    float* attn; cudaGetSymbolAddress((void**)&attn, g_attn);

    const size_t attn_smem = (size_t)ATTN_SMEM_FLOATS * sizeof(float); // ~204 KB
    cudaFuncSetAttribute(attn_kernel, cudaFuncAttributeMaxDynamicSharedMemorySize,
                         (int)attn_smem);

    // 1) QKV projection (+bias, Q rows pre-scaled by 1/sqrt(32))
    {
        dim3 grid(HW / 128, DQKV / 128, BATCH); // (8, 6, 8)
        gemm_bias_kernel<CIN><<<grid, 256>>>(w_qkv, x, b_qkv, qkv,
                                             DQKV, HW, 256, 0.17677669529663687f);
    }

    // 2) Fused logits -> head-softmax -> AV (writes reference-reshape layout)
    {
        dim3 grid(HW / QT, BATCH); // (16, 8)
        attn_kernel<<<grid, 256, attn_smem>>>(attn);
    }

    // 3) Output projection (+bias)
    {
        dim3 grid(HW / 128, COUT / 128, BATCH); // (8, 4, 8)
        gemm_bias_kernel<DVDIM><<<grid, 256>>>(w_attn, attn, b_attn, out,
                                               COUT, HW, 0, 1.0f);
    }
}

// round 4
// speedup vs baseline: 1.1940x; 1.1940x over previous
#include <cuda_runtime.h>
#include <cuda_bf16.h>
#include <cstdint>
#include <math.h>

#define BATCH 8
#define CIN   512
#define HW    1024
#define DQKV  768
#define DVDIM 256
#define COUT  512

// ---------------- scratch (static device globals; allocation-free rule) ----
__device__ float g_qkv[(size_t)BATCH * DQKV * HW];   // 24 MB [b][o][s]
__device__ float g_attn[(size_t)BATCH * DVDIM * HW]; // 8 MB  [b][c][s] (ref-reshape layout)

__device__ __nv_bfloat16 g_wqkv_hi[DQKV * CIN],  g_wqkv_lo[DQKV * CIN];
__device__ __nv_bfloat16 g_wattn_hi[COUT * DVDIM], g_wattn_lo[COUT * DVDIM];
__device__ __nv_bfloat16 g_xt_hi[(size_t)BATCH * HW * CIN],  g_xt_lo[(size_t)BATCH * HW * CIN];    // [b][s][c]
__device__ __nv_bfloat16 g_at_hi[(size_t)BATCH * HW * DVDIM], g_at_lo[(size_t)BATCH * HW * DVDIM]; // [b][s][c]

// ---------------- helpers ---------------------------------------------------
__device__ __forceinline__ uint32_t smem_u32(const void* p) {
    uint32_t a;
    asm("{ .reg .u64 t; cvta.to.shared.u64 t, %1; cvt.u32.u64 %0, t; }" : "=r"(a) : "l"(p));
    return a;
}

#define LDSM_X4(r0, r1, r2, r3, addr)                                           \
    asm volatile("ldmatrix.sync.aligned.m8n8.x4.shared.b16 {%0,%1,%2,%3}, [%4];"\
                 : "=r"(r0), "=r"(r1), "=r"(r2), "=r"(r3) : "r"(addr))
#define LDSM_X2(r0, r1, addr)                                                   \
    asm volatile("ldmatrix.sync.aligned.m8n8.x2.shared.b16 {%0,%1}, [%2];"      \
                 : "=r"(r0), "=r"(r1) : "r"(addr))

__device__ __forceinline__ void mma_bf16(float* c, const uint32_t* a, const uint32_t* b) {
    asm volatile("mma.sync.aligned.m16n8k16.row.col.f32.bf16.bf16.f32 "
                 "{%0,%1,%2,%3}, {%4,%5,%6,%7}, {%8,%9}, {%0,%1,%2,%3};"
                 : "+f"(c[0]), "+f"(c[1]), "+f"(c[2]), "+f"(c[3])
                 : "r"(a[0]), "r"(a[1]), "r"(a[2]), "r"(a[3]), "r"(b[0]), "r"(b[1]));
}

// ---------------- conversion kernels ---------------------------------------
__global__ void split_kernel(const float* __restrict__ w,
                             __nv_bfloat16* __restrict__ hi,
                             __nv_bfloat16* __restrict__ lo, int n) {
    int i = blockIdx.x * 256 + threadIdx.x;
    if (i < n) {
        float v = w[i];
        __nv_bfloat16 h = __float2bfloat16(v);
        hi[i] = h;
        lo[i] = __float2bfloat16(v - __bfloat162float(h));
    }
}

// X[b][C][S] -> out[b][S][C] bf16 hi/lo (transpose + split)
__global__ void tsplit_kernel(const float* __restrict__ X,
                              __nv_bfloat16* __restrict__ hi,
                              __nv_bfloat16* __restrict__ lo, int C, int S) {
    __shared__ float t[32][33];
    const int b = blockIdx.z;
    const int c0 = blockIdx.y * 32, s0 = blockIdx.x * 32;
    const int tx = threadIdx.x, ty = threadIdx.y; // 32 x 8
    const float* Xb = X + (size_t)b * C * S;
    #pragma unroll
    for (int i = 0; i < 32; i += 8)
        t[ty + i][tx] = Xb[(size_t)(c0 + ty + i) * S + s0 + tx];
    __syncthreads();
    const size_t ob = (size_t)b * S * C;
    #pragma unroll
    for (int i = 0; i < 32; i += 8) {
        float v = t[tx][ty + i];
        __nv_bfloat16 h = __float2bfloat16(v);
        size_t idx = ob + (size_t)(s0 + ty + i) * C + c0 + tx;
        hi[idx] = h;
        lo[idx] = __float2bfloat16(v - __bfloat162float(h));
    }
}

// ---------------- HMMA split-bf16 GEMM --------------------------------------
// C[b][o][s] = sum_c W[o][c] X[c][s] + bias[o]  (rows o<scale_limit scaled)
// A = W (K-major [o][c]), B = Xt (K-major [s][c]).
// 128x128 CTA tile, 8 warps (2x4), warp tile 64x32, BK=64 chunks.
// smem rows padded to 72 bf16 (144 B) -> conflict-free ldmatrix.
#define BK      64
#define RPAD    72          // bf16 per smem row
#define TILE_B  (128 * RPAD * 2)   // 18432 bytes per buffer
#define GM_SMEM (4 * TILE_B)       // Ahi, Alo, Bhi, Blo = 73728

template<int K>
__global__ __launch_bounds__(256) void gemm_mma(
    const __nv_bfloat16* __restrict__ Ahi, const __nv_bfloat16* __restrict__ Alo,
    const __nv_bfloat16* __restrict__ Bhi_all, const __nv_bfloat16* __restrict__ Blo_all,
    const float* __restrict__ bias, float* __restrict__ C_all,
    int M, int N, int scale_limit, float scale)
{
    extern __shared__ char smem[];
    char* sAhi = smem;
    char* sAlo = smem + TILE_B;
    char* sBhi = smem + 2 * TILE_B;
    char* sBlo = smem + 3 * TILE_B;

    const int tid  = threadIdx.x;
    const int wid  = tid >> 5;
    const int lane = tid & 31;
    const int wm = wid >> 2;       // 0..1 -> 64-row band
    const int wn = wid & 3;        // 0..3 -> 32-col band
    const int b  = blockIdx.z, m0 = blockIdx.y * 128, n0 = blockIdx.x * 128;

    const __nv_bfloat16* Bhi = Bhi_all + (size_t)b * N * K;
    const __nv_bfloat16* Blo = Blo_all + (size_t)b * N * K;
    float* C = C_all + (size_t)b * M * N;

    // ldmatrix per-lane address components
    const int a_row  = wm * 64 + (lane & 7) + ((lane >> 3) & 1) * 8; // + mt*16
    const int a_koff = ((lane >> 3) >> 1) * 8;                        // bf16 units
    const int b_row  = wn * 32 + (lane & 7);                          // + nt*8
    const int b_koff = ((lane >> 3) & 1) * 8;

    const uint32_t sAhi_u = smem_u32(sAhi), sAlo_u = smem_u32(sAlo);
    const uint32_t sBhi_u = smem_u32(sBhi), sBlo_u = smem_u32(sBlo);

    float acc[4][4][4] = {};   // [mt][nt][c0..c3]

    for (int c0k = 0; c0k < K; c0k += BK) {
        // stage 4 tiles: 128 rows x 64 bf16 each (uint4 = 8 bf16 per store)
        #pragma unroll
        for (int it = 0; it < 4; it++) {
            const int slot = it * 256 + tid;     // 0..1023
            const int cg = slot & 7;             // 16B group
            const int r  = slot >> 3;            // row
            const uint32_t so = (uint32_t)(r * (RPAD * 2) + cg * 16);
            const size_t ao = (size_t)(m0 + r) * K + c0k + cg * 8;
            const size_t bo = (size_t)(n0 + r) * K + c0k + cg * 8;
            *(uint4*)(sAhi + so) = *(const uint4*)&Ahi[ao];
            *(uint4*)(sAlo + so) = *(const uint4*)&Alo[ao];
            *(uint4*)(sBhi + so) = *(const uint4*)&Bhi[bo];
            *(uint4*)(sBlo + so) = *(const uint4*)&Blo[bo];
        }
        __syncthreads();

        #pragma unroll
        for (int ks = 0; ks < BK / 16; ks++) {
            const int kb = ks * 16;
            // B fragments (hi & lo) for the 4 n-tiles
            uint32_t bh[4][2], bl[4][2];
            #pragma unroll
            for (int nt = 0; nt < 4; nt++) {
                const uint32_t off = (uint32_t)((b_row + nt * 8) * (RPAD * 2) +
                                                (kb + b_koff) * 2);
                LDSM_X2(bh[nt][0], bh[nt][1], sBhi_u + off);
                LDSM_X2(bl[nt][0], bl[nt][1], sBlo_u + off);
            }
            #pragma unroll
            for (int mt = 0; mt < 4; mt++) {
                const uint32_t off = (uint32_t)((a_row + mt * 16) * (RPAD * 2) +
                                                (kb + a_koff) * 2);
                uint32_t ah[4], al[4];
                LDSM_X4(ah[0], ah[1], ah[2], ah[3], sAhi_u + off);
                LDSM_X4(al[0], al[1], al[2], al[3], sAlo_u + off);
                #pragma unroll
                for (int nt = 0; nt < 4; nt++) {
                    mma_bf16(acc[mt][nt], ah, bh[nt]);   // hi*hi
                    mma_bf16(acc[mt][nt], ah, bl[nt]);   // hi*lo
                    mma_bf16(acc[mt][nt], al, bh[nt]);   // lo*hi
                }
            }
        }
        __syncthreads();
    }

    // epilogue: C fragment (c0,c1)=(row l/4, col (l%4)*2+{0,1}), (c2,c3)=row+8
    const int col0 = n0 + wn * 32 + (lane & 3) * 2;
    #pragma unroll
    for (int mt = 0; mt < 4; mt++) {
        const int r0 = m0 + wm * 64 + mt * 16 + (lane >> 2);
        const int r1 = r0 + 8;
        const float bv0 = bias[r0], bv1 = bias[r1];
        const float sc0 = (r0 < scale_limit) ? scale : 1.0f;
        const float sc1 = (r1 < scale_limit) ? scale : 1.0f;
        #pragma unroll
        for (int nt = 0; nt < 4; nt++) {
            float2 v0, v1;
            v0.x = (acc[mt][nt][0] + bv0) * sc0;
            v0.y = (acc[mt][nt][1] + bv0) * sc0;
            v1.x = (acc[mt][nt][2] + bv1) * sc1;
            v1.y = (acc[mt][nt][3] + bv1) * sc1;
            *(float2*)&C[(size_t)r0 * N + col0 + nt * 8] = v0;
            *(float2*)&C[(size_t)r1 * N + col0 + nt * 8] = v1;
        }
    }
}

// ---------------- fused attention (unchanged from passing R2) --------------
#define QT   64
#define KTS  32
#define QPAD 260
#define KPAD 36
#define WPAD 33
#define ATTN_SMEM_FLOATS (64*QPAD + 256*KPAD + 32*QPAD + 8*64*WPAD)

__global__ __launch_bounds__(256) void attn_kernel(float* __restrict__ attn_out)
{
    extern __shared__ float sm[];
    float* Qs = sm;
    float* Ks = Qs + 64 * QPAD;
    float* Vs = Ks + 256 * KPAD;
    float* Wt = Vs + 32 * QPAD;

    const int b     = blockIdx.y;
    const int qbase = blockIdx.x * QT;
    const int tid   = threadIdx.x;
    const float* qkv = g_qkv + (size_t)b * DQKV * HW;

    for (int idx = tid; idx < QT * 256; idx += 256) {
        const int dim = idx >> 6;
        const int q   = idx & 63;
        Qs[q * QPAD + dim] = qkv[(size_t)dim * HW + qbase + q];
    }

    const int qg = tid >> 3;
    const int kg = tid & 7;
    const int dg = tid & 7;
    const int q0 = qg * 2;
    const int k0 = kg * 4;

    float acc[8][2][4] = {};

    for (int kt = 0; kt < HW; kt += KTS) {
        __syncthreads();
        for (int idx = tid; idx < 256 * KTS; idx += 256) {
            const int dim = idx >> 5;
            const int k   = idx & 31;
            Ks[dim * KPAD + k] = qkv[(size_t)(256 + dim) * HW + kt + k];
        }
        for (int idx = tid; idx < 256 * KTS; idx += 256) {
            const int dim = idx >> 5;
            const int k   = idx & 31;
            Vs[k * QPAD + dim] = qkv[(size_t)(512 + dim) * HW + kt + k];
        }
        __syncthreads();

        float lg[8][2][4] = {};
        #pragma unroll
        for (int h = 0; h < 8; h++) {
            const float* Kh = &Ks[(h * 32) * KPAD + k0];
            const float* Q0 = &Qs[q0 * QPAD + h * 32];
            const float* Q1 = &Qs[(q0 + 1) * QPAD + h * 32];
            #pragma unroll 8
            for (int d = 0; d < 32; d++) {
                const float4 kv = *(const float4*)&Kh[d * KPAD];
                const float qa = Q0[d];
                const float qb = Q1[d];
                lg[h][0][0] += qa * kv.x; lg[h][0][1] += qa * kv.y;
                lg[h][0][2] += qa * kv.z; lg[h][0][3] += qa * kv.w;
                lg[h][1][0] += qb * kv.x; lg[h][1][1] += qb * kv.y;
                lg[h][1][2] += qb * kv.z; lg[h][1][3] += qb * kv.w;
            }
        }

        #pragma unroll
        for (int qi = 0; qi < 2; qi++) {
            #pragma unroll
            for (int kj = 0; kj < 4; kj++) {
                float m = lg[0][qi][kj];
                #pragma unroll
                for (int h = 1; h < 8; h++) m = fmaxf(m, lg[h][qi][kj]);
                float e[8], s = 0.0f;
                #pragma unroll
                for (int h = 0; h < 8; h++) { e[h] = __expf(lg[h][qi][kj] - m); s += e[h]; }
                const float inv = 1.0f / s;
                #pragma unroll
                for (int h = 0; h < 8; h++)
                    Wt[(h * 64 + q0 + qi) * WPAD + k0 + kj] = e[h] * inv;
            }
        }
        __syncthreads();

        #pragma unroll
        for (int h = 0; h < 8; h++) {
            const float* Wh0 = &Wt[(h * 64 + q0) * WPAD];
            const float* Wh1 = &Wt[(h * 64 + q0 + 1) * WPAD];
            const float* Vh  = &Vs[h * 32 + dg * 4];
            #pragma unroll 8
            for (int k = 0; k < KTS; k++) {
                const float4 v = *(const float4*)&Vh[k * QPAD];
                const float w0 = Wh0[k];
                const float w1 = Wh1[k];
                acc[h][0][0] += w0 * v.x; acc[h][0][1] += w0 * v.y;
                acc[h][0][2] += w0 * v.z; acc[h][0][3] += w0 * v.w;
                acc[h][1][0] += w1 * v.x; acc[h][1][1] += w1 * v.y;
                acc[h][1][2] += w1 * v.z; acc[h][1][3] += w1 * v.w;
            }
        }
    }

    float* ab = attn_out + (size_t)b * DVDIM * HW;
    #pragma unroll
    for (int h = 0; h < 8; h++) {
        #pragma unroll
        for (int qi = 0; qi < 2; qi++) {
            const int qq = qbase + q0 + qi;
            const int ch = h * 32 + (qq >> 5);
            const int sp = (qq & 31) * 32 + dg * 4;
            float4 v;
            v.x = acc[h][qi][0]; v.y = acc[h][qi][1];
            v.z = acc[h][qi][2]; v.w = acc[h][qi][3];
            *(float4*)&ab[(size_t)ch * HW + sp] = v;
        }
    }
}

// ---------------------------------------------------------------------------
extern "C" void kernel_launch(void* const* d_in, const int* in_sizes, int n_in,
                              void* d_out, int out_size)
{
    const float* x      = (const float*)d_in[0];
    const float* w_qkv  = (const float*)d_in[1];
    const float* b_qkv  = (const float*)d_in[2];
    const float* w_attn = (const float*)d_in[3];
    const float* b_attn = (const float*)d_in[4];
    float* out = (float*)d_out;

    float* qkv;  cudaGetSymbolAddress((void**)&qkv,  g_qkv);
    float* attn; cudaGetSymbolAddress((void**)&attn, g_attn);
    __nv_bfloat16 *wqh, *wql, *wah, *wal, *xth, *xtl, *ath, *atl;
    cudaGetSymbolAddress((void**)&wqh, g_wqkv_hi);
    cudaGetSymbolAddress((void**)&wql, g_wqkv_lo);
    cudaGetSymbolAddress((void**)&wah, g_wattn_hi);
    cudaGetSymbolAddress((void**)&wal, g_wattn_lo);
    cudaGetSymbolAddress((void**)&xth, g_xt_hi);
    cudaGetSymbolAddress((void**)&xtl, g_xt_lo);
    cudaGetSymbolAddress((void**)&ath, g_at_hi);
    cudaGetSymbolAddress((void**)&atl, g_at_lo);

    const size_t attn_smem = (size_t)ATTN_SMEM_FLOATS * sizeof(float);
    cudaFuncSetAttribute(attn_kernel, cudaFuncAttributeMaxDynamicSharedMemorySize,
                         (int)attn_smem);
    cudaFuncSetAttribute(gemm_mma<CIN>, cudaFuncAttributeMaxDynamicSharedMemorySize,
                         GM_SMEM);
    cudaFuncSetAttribute(gemm_mma<DVDIM>, cudaFuncAttributeMaxDynamicSharedMemorySize,
                         GM_SMEM);

    // 0) precision-split weights; transpose+split x
    split_kernel<<<(DQKV * CIN + 255) / 256, 256>>>(w_qkv, wqh, wql, DQKV * CIN);
    split_kernel<<<(COUT * DVDIM + 255) / 256, 256>>>(w_attn, wah, wal, COUT * DVDIM);
    {
        dim3 grid(HW / 32, CIN / 32, BATCH);
        tsplit_kernel<<<grid, dim3(32, 8)>>>(x, xth, xtl, CIN, HW);
    }

    // 1) QKV projection on HMMA (+bias, Q rows pre-scaled)
    {
        dim3 grid(HW / 128, DQKV / 128, BATCH); // (8,6,8)
        gemm_mma<CIN><<<grid, 256, GM_SMEM>>>(wqh, wql, xth, xtl, b_qkv, qkv,
                                              DQKV, HW, 256, 0.17677669529663687f);
    }

    // 2) fused logits -> head-softmax -> AV (unchanged)
    {
        dim3 grid(HW / QT, BATCH);
        attn_kernel<<<grid, 256, attn_smem>>>(attn);
    }

    // 2.5) transpose+split attention output for GEMM3's B operand
    {
        dim3 grid(HW / 32, DVDIM / 32, BATCH);
        tsplit_kernel<<<grid, dim3(32, 8)>>>(attn, ath, atl, DVDIM, HW);
    }

    // 3) output projection on HMMA (+bias)
    {
        dim3 grid(HW / 128, COUT / 128, BATCH); // (8,4,8)
        gemm_mma<DVDIM><<<grid, 256, GM_SMEM>>>(wah, wal, ath, atl, b_attn, out,
                                                COUT, HW, 0, 1.0f);
    }
}